// round 5
// baseline (speedup 1.0000x reference)
#include <cuda_runtime.h>
#include <cuda_fp16.h>
#include <cuda_bf16.h>

// Problem constants (fixed shapes per reference)
#define N_NODES   100000
#define N_EDGES   1600000
#define IN_FEATS  128
#define OUT_FEATS 64

// Scratch: projected features h in fp16 (12.8 MB)
__device__ __half2 g_h16[(size_t)N_NODES * (OUT_FEATS / 2)];
// Scratch: int32 edge indices (dtype-normalized)
__device__ int g_src32[N_EDGES];
__device__ int g_dst32[N_EDGES];
// Dtype detection flag: nonzero => index buffers are int32
__device__ unsigned int g_is_i32;

// ---------------------------------------------------------------------------
// Vector reduction helper: red.global.add.v4.f32 on sm_90+, scalar fallback.
// ---------------------------------------------------------------------------
__device__ __forceinline__ void red_add_v4(float* p, float x, float y, float z, float w) {
#if defined(__CUDA_ARCH__) && (__CUDA_ARCH__ >= 900)
    asm volatile("red.global.add.v4.f32 [%0], {%1, %2, %3, %4};"
                 :: "l"(p), "f"(x), "f"(y), "f"(z), "f"(w)
                 : "memory");
#else
    atomicAdd(p + 0, x);
    atomicAdd(p + 1, y);
    atomicAdd(p + 2, z);
    atomicAdd(p + 3, w);
#endif
}

// ---------------------------------------------------------------------------
// Kernel 1: zero output accumulator + clear detection flag
// ---------------------------------------------------------------------------
__global__ __launch_bounds__(256) void zero_kernel(float4* out, int n4) {
    int i = blockIdx.x * blockDim.x + threadIdx.x;
    if (i == 0) g_is_i32 = 0u;
    if (i < n4) out[i] = make_float4(0.f, 0.f, 0.f, 0.f);
}

// ---------------------------------------------------------------------------
// Kernel 1b: dtype detection. Odd 4B words within the first 4*N_EDGES bytes
// are int64 high words (all zero since idx < 100000) or real int32 indices.
// ---------------------------------------------------------------------------
__global__ __launch_bounds__(256) void detect_kernel(const unsigned int* __restrict__ buf) {
    unsigned int lor = 0;
    int nhalf = N_EDGES / 2;
    for (int i = blockIdx.x * blockDim.x + threadIdx.x;
         i < nhalf;
         i += gridDim.x * blockDim.x) {
        lor |= buf[2 * i + 1];
    }
    unsigned int any = __ballot_sync(0xffffffffu, lor != 0u);
    if ((threadIdx.x & 31) == 0 && any) g_is_i32 = 1u;  // same-value store, race-free
}

// ---------------------------------------------------------------------------
// Kernel 1c: normalize indices to int32 with bounds clamp.
// ---------------------------------------------------------------------------
__global__ __launch_bounds__(256) void convert_kernel(const void* __restrict__ srcb,
                                                      const void* __restrict__ dstb) {
    int i = blockIdx.x * blockDim.x + threadIdx.x;
    if (i >= N_EDGES) return;
    unsigned int i32 = g_is_i32;
    int s, d;
    if (i32) {
        s = ((const int*)srcb)[i];
        d = ((const int*)dstb)[i];
    } else {
        s = (int)((const long long*)srcb)[i];
        d = (int)((const long long*)dstb)[i];
    }
    g_src32[i] = ((unsigned)s < (unsigned)N_NODES) ? s : 0;
    g_dst32[i] = ((unsigned)d < (unsigned)N_NODES) ? d : 0;
}

// ---------------------------------------------------------------------------
// Kernel 2: tiled fp32 GEMM  h[n][o] = sum_k feat[n][k] * W[o][k] + b[o]
// 128 threads/block, tile = 128 nodes x 64 outs, K chunks of 32.
// Each thread: 8 nodes x 8 outs = 64 accumulators; 4 LDS.128 per 64 FFMA.
// smem transposed [k][col] with XOR swizzle (col ^ ((k>>2&3)<<3)) to avoid
// 8-way store conflicts while keeping 16B-aligned vector loads.
// Epilogue stores h in fp16 (one uint4 per thread per node).
// ---------------------------------------------------------------------------
#define MT 128
#define KT 32

__global__ __launch_bounds__(128) void gemm_kernel(
    const float* __restrict__ feat,
    const float* __restrict__ W,
    const float* __restrict__ b)
{
    __shared__ float sf[KT][MT];        // feat tile: [k][node^swz]  (16KB)
    __shared__ float sw[KT][OUT_FEATS]; // W tile:    [k][out ^swz]  (8KB)

    const int tid    = threadIdx.x;
    const int block0 = blockIdx.x * MT;
    const int g_n    = tid & 15;        // 16 node groups
    const int g_o    = tid >> 4;        // 8 out groups
    const int nr     = g_n * 8;         // 8 consecutive nodes
    const int oc     = g_o * 8;         // 8 consecutive outs

    float acc[8][8];
#pragma unroll
    for (int i = 0; i < 8; i++)
#pragma unroll
        for (int j = 0; j < 8; j++) acc[i][j] = 0.f;

    for (int kb = 0; kb < IN_FEATS; kb += KT) {
        // --- feat tile: 128 nodes x 32 k = 1024 float4, 8 per thread ---
#pragma unroll
        for (int t = 0; t < 8; t++) {
            int l    = tid + t * 128;   // 0..1023
            int node = l >> 3;          // 0..127
            int kq   = l & 7;           // float4 index within chunk
            float4 v = make_float4(0.f, 0.f, 0.f, 0.f);
            int gn = block0 + node;
            if (gn < N_NODES)
                v = *(const float4*)(feat + (size_t)gn * IN_FEATS + kb + kq * 4);
            int col = node ^ ((kq & 3) << 3);   // swizzle
            sf[kq * 4 + 0][col] = v.x;
            sf[kq * 4 + 1][col] = v.y;
            sf[kq * 4 + 2][col] = v.z;
            sf[kq * 4 + 3][col] = v.w;
        }
        // --- W tile: 64 outs x 32 k = 512 float4, 4 per thread ---
#pragma unroll
        for (int t = 0; t < 4; t++) {
            int l  = tid + t * 128;     // 0..511
            int o  = l >> 3;            // 0..63
            int kq = l & 7;
            float4 v = *(const float4*)(W + (size_t)o * IN_FEATS + kb + kq * 4);
            int col = o ^ ((kq & 3) << 3);
            sw[kq * 4 + 0][col] = v.x;
            sw[kq * 4 + 1][col] = v.y;
            sw[kq * 4 + 2][col] = v.z;
            sw[kq * 4 + 3][col] = v.w;
        }
        __syncthreads();

#pragma unroll
        for (int kk = 0; kk < KT; kk++) {
            int swz = ((kk >> 2) & 3) << 3;
            float a[8], w[8];
            *(float4*)&a[0] = *(const float4*)&sf[kk][(nr ^ swz)];
            *(float4*)&a[4] = *(const float4*)&sf[kk][(nr ^ swz) + 4];
            *(float4*)&w[0] = *(const float4*)&sw[kk][(oc ^ swz)];
            *(float4*)&w[4] = *(const float4*)&sw[kk][(oc ^ swz) + 4];
#pragma unroll
            for (int i = 0; i < 8; i++)
#pragma unroll
                for (int j = 0; j < 8; j++)
                    acc[i][j] += a[i] * w[j];
        }
        __syncthreads();
    }

    // epilogue: bias, convert to fp16, one 16B store per node
    float bias[8];
    *(float4*)&bias[0] = *(const float4*)(b + oc);
    *(float4*)&bias[4] = *(const float4*)(b + oc + 4);
#pragma unroll
    for (int i = 0; i < 8; i++) {
        int gn = block0 + nr + i;
        if (gn < N_NODES) {
            __half2 p[4];
#pragma unroll
            for (int j = 0; j < 4; j++)
                p[j] = __floats2half2_rn(acc[i][2 * j] + bias[2 * j],
                                         acc[i][2 * j + 1] + bias[2 * j + 1]);
            *(uint4*)(g_h16 + (size_t)gn * (OUT_FEATS / 2) + g_o * 4) = *(uint4*)p;
        }
    }
}

// ---------------------------------------------------------------------------
// Kernel 3: edge scatter. 8 threads per edge, each owns 8 halves (16B) of the
// fp16 h row. Gather 128B/edge (coalesced), convert+scale fp32, two vector
// REDs (32B) into fp32 out[dst].
// ---------------------------------------------------------------------------
__global__ __launch_bounds__(256) void edge_kernel(
    const float* __restrict__ e,
    float*       __restrict__ out)
{
    long long idx = (long long)blockIdx.x * blockDim.x + threadIdx.x;
    int eid  = (int)(idx >> 3);
    int lane = (int)(idx & 7);
    if (eid >= N_EDGES) return;

    int   s = g_src32[eid];
    int   d = g_dst32[eid];
    float w = e[eid];

    uint4 raw = *(const uint4*)(g_h16 + (size_t)s * (OUT_FEATS / 2) + lane * 4);
    float2 f0 = __half22float2(*(__half2*)&raw.x);
    float2 f1 = __half22float2(*(__half2*)&raw.y);
    float2 f2 = __half22float2(*(__half2*)&raw.z);
    float2 f3 = __half22float2(*(__half2*)&raw.w);

    float* p = out + (size_t)d * OUT_FEATS + lane * 8;
    red_add_v4(p,     f0.x * w, f0.y * w, f1.x * w, f1.y * w);
    red_add_v4(p + 4, f2.x * w, f2.y * w, f3.x * w, f3.y * w);
}

// ---------------------------------------------------------------------------
// Kernel 4: in-place relu
// ---------------------------------------------------------------------------
__global__ __launch_bounds__(256) void relu_kernel(float4* out, int n4) {
    int i = blockIdx.x * blockDim.x + threadIdx.x;
    if (i < n4) {
        float4 v = out[i];
        v.x = fmaxf(v.x, 0.f);
        v.y = fmaxf(v.y, 0.f);
        v.z = fmaxf(v.z, 0.f);
        v.w = fmaxf(v.w, 0.f);
        out[i] = v;
    }
}

// ---------------------------------------------------------------------------
extern "C" void kernel_launch(void* const* d_in, const int* in_sizes, int n_in,
                              void* d_out, int out_size)
{
    const float* feat = (const float*)d_in[0];
    const void*  src  = d_in[1];
    const void*  dst  = d_in[2];
    const float* e    = (const float*)d_in[3];
    const float* W_w  = (const float*)d_in[4];
    const float* W_b  = (const float*)d_in[5];
    float*       out  = (float*)d_out;

    const int n4 = (N_NODES * OUT_FEATS) / 4;   // 1.6M float4

    // 1. zero accumulator + clear flag
    zero_kernel<<<(n4 + 255) / 256, 256>>>((float4*)out, n4);

    // 1b. detect index dtype (int32 vs int64)
    detect_kernel<<<1024, 256>>>((const unsigned int*)src);

    // 1c. normalize indices to int32
    convert_kernel<<<(N_EDGES + 255) / 256, 256>>>(src, dst);

    // 2. dense projection into g_h16 (fp16)
    gemm_kernel<<<(N_NODES + MT - 1) / MT, 128>>>(feat, W_w, W_b);

    // 3. edge gather/scale/scatter-add (8 threads per edge)
    {
        long long total_threads = (long long)N_EDGES * 8LL;
        int blocks = (int)((total_threads + 255) / 256);   // 50000 blocks
        edge_kernel<<<blocks, 256>>>(e, out);
    }

    // 4. relu in place
    relu_kernel<<<(n4 + 255) / 256, 256>>>((float4*)out, n4);
}

// round 6
// speedup vs baseline: 1.1236x; 1.1236x over previous
#include <cuda_runtime.h>
#include <cuda_fp16.h>
#include <cuda_bf16.h>

// Problem constants (fixed shapes per reference)
#define N_NODES   100000
#define N_EDGES   1600000
#define IN_FEATS  128
#define OUT_FEATS 64

// Scratch: projected features h in fp16 (12.8 MB)
__device__ __half2 g_h16[(size_t)N_NODES * (OUT_FEATS / 2)];
// Scratch: int32 edge indices (dtype-normalized)
__device__ int g_src32[N_EDGES];
__device__ int g_dst32[N_EDGES];
// Dtype detection flag: nonzero => index buffers are int32
__device__ unsigned int g_is_i32;

// ---------------------------------------------------------------------------
// Vector reduction helper: red.global.add.v4.f32 on sm_90+, scalar fallback.
// ---------------------------------------------------------------------------
__device__ __forceinline__ void red_add_v4(float* p, float x, float y, float z, float w) {
#if defined(__CUDA_ARCH__) && (__CUDA_ARCH__ >= 900)
    asm volatile("red.global.add.v4.f32 [%0], {%1, %2, %3, %4};"
                 :: "l"(p), "f"(x), "f"(y), "f"(z), "f"(w)
                 : "memory");
#else
    atomicAdd(p + 0, x);
    atomicAdd(p + 1, y);
    atomicAdd(p + 2, z);
    atomicAdd(p + 3, w);
#endif
}

// ---------------------------------------------------------------------------
// Kernel 1: zero output accumulator + clear detection flag
// ---------------------------------------------------------------------------
__global__ __launch_bounds__(256) void zero_kernel(float4* out, int n4) {
    int i = blockIdx.x * blockDim.x + threadIdx.x;
    if (i == 0) g_is_i32 = 0u;
    if (i < n4) out[i] = make_float4(0.f, 0.f, 0.f, 0.f);
}

// ---------------------------------------------------------------------------
// Kernel 1b: dtype detection. Odd 4B words within the first 4*N_EDGES bytes
// are int64 high words (all zero since idx < 100000) or real int32 indices.
// ---------------------------------------------------------------------------
__global__ __launch_bounds__(256) void detect_kernel(const unsigned int* __restrict__ buf) {
    unsigned int lor = 0;
    int nhalf = N_EDGES / 2;
    for (int i = blockIdx.x * blockDim.x + threadIdx.x;
         i < nhalf;
         i += gridDim.x * blockDim.x) {
        lor |= buf[2 * i + 1];
    }
    unsigned int any = __ballot_sync(0xffffffffu, lor != 0u);
    if ((threadIdx.x & 31) == 0 && any) g_is_i32 = 1u;  // same-value store, race-free
}

// ---------------------------------------------------------------------------
// Kernel 1c: normalize indices to int32 with bounds clamp.
// ---------------------------------------------------------------------------
__global__ __launch_bounds__(256) void convert_kernel(const void* __restrict__ srcb,
                                                      const void* __restrict__ dstb) {
    int i = blockIdx.x * blockDim.x + threadIdx.x;
    if (i >= N_EDGES) return;
    unsigned int i32 = g_is_i32;
    int s, d;
    if (i32) {
        s = ((const int*)srcb)[i];
        d = ((const int*)dstb)[i];
    } else {
        s = (int)((const long long*)srcb)[i];
        d = (int)((const long long*)dstb)[i];
    }
    g_src32[i] = ((unsigned)s < (unsigned)N_NODES) ? s : 0;
    g_dst32[i] = ((unsigned)d < (unsigned)N_NODES) ? d : 0;
}

// ---------------------------------------------------------------------------
// Kernel 2: tiled fp32 GEMM  h[n][o] = sum_k feat[n][k] * W[o][k] + b[o]
// 128 threads/block, tile = 128 nodes x 64 outs, K chunks of 32.
// Each thread: 8 nodes x 8 outs = 64 accumulators; 4 LDS.128 per 64 FFMA.
// XOR-swizzled smem; epilogue stores h in fp16.
// (At the fp32-FFMA issue roofline; do not touch.)
// ---------------------------------------------------------------------------
#define MT 128
#define KT 32

__global__ __launch_bounds__(128) void gemm_kernel(
    const float* __restrict__ feat,
    const float* __restrict__ W,
    const float* __restrict__ b)
{
    __shared__ float sf[KT][MT];        // feat tile: [k][node^swz]  (16KB)
    __shared__ float sw[KT][OUT_FEATS]; // W tile:    [k][out ^swz]  (8KB)

    const int tid    = threadIdx.x;
    const int block0 = blockIdx.x * MT;
    const int g_n    = tid & 15;        // 16 node groups
    const int g_o    = tid >> 4;        // 8 out groups
    const int nr     = g_n * 8;         // 8 consecutive nodes
    const int oc     = g_o * 8;         // 8 consecutive outs

    float acc[8][8];
#pragma unroll
    for (int i = 0; i < 8; i++)
#pragma unroll
        for (int j = 0; j < 8; j++) acc[i][j] = 0.f;

    for (int kb = 0; kb < IN_FEATS; kb += KT) {
        // --- feat tile: 128 nodes x 32 k = 1024 float4, 8 per thread ---
#pragma unroll
        for (int t = 0; t < 8; t++) {
            int l    = tid + t * 128;   // 0..1023
            int node = l >> 3;          // 0..127
            int kq   = l & 7;           // float4 index within chunk
            float4 v = make_float4(0.f, 0.f, 0.f, 0.f);
            int gn = block0 + node;
            if (gn < N_NODES)
                v = *(const float4*)(feat + (size_t)gn * IN_FEATS + kb + kq * 4);
            int col = node ^ ((kq & 3) << 3);   // swizzle
            sf[kq * 4 + 0][col] = v.x;
            sf[kq * 4 + 1][col] = v.y;
            sf[kq * 4 + 2][col] = v.z;
            sf[kq * 4 + 3][col] = v.w;
        }
        // --- W tile: 64 outs x 32 k = 512 float4, 4 per thread ---
#pragma unroll
        for (int t = 0; t < 4; t++) {
            int l  = tid + t * 128;     // 0..511
            int o  = l >> 3;            // 0..63
            int kq = l & 7;
            float4 v = *(const float4*)(W + (size_t)o * IN_FEATS + kb + kq * 4);
            int col = o ^ ((kq & 3) << 3);
            sw[kq * 4 + 0][col] = v.x;
            sw[kq * 4 + 1][col] = v.y;
            sw[kq * 4 + 2][col] = v.z;
            sw[kq * 4 + 3][col] = v.w;
        }
        __syncthreads();

#pragma unroll
        for (int kk = 0; kk < KT; kk++) {
            int swz = ((kk >> 2) & 3) << 3;
            float a[8], w[8];
            *(float4*)&a[0] = *(const float4*)&sf[kk][(nr ^ swz)];
            *(float4*)&a[4] = *(const float4*)&sf[kk][(nr ^ swz) + 4];
            *(float4*)&w[0] = *(const float4*)&sw[kk][(oc ^ swz)];
            *(float4*)&w[4] = *(const float4*)&sw[kk][(oc ^ swz) + 4];
#pragma unroll
            for (int i = 0; i < 8; i++)
#pragma unroll
                for (int j = 0; j < 8; j++)
                    acc[i][j] += a[i] * w[j];
        }
        __syncthreads();
    }

    // epilogue: bias, convert to fp16, one 16B store per node
    float bias[8];
    *(float4*)&bias[0] = *(const float4*)(b + oc);
    *(float4*)&bias[4] = *(const float4*)(b + oc + 4);
#pragma unroll
    for (int i = 0; i < 8; i++) {
        int gn = block0 + nr + i;
        if (gn < N_NODES) {
            __half2 p[4];
#pragma unroll
            for (int j = 0; j < 4; j++)
                p[j] = __floats2half2_rn(acc[i][2 * j] + bias[2 * j],
                                         acc[i][2 * j + 1] + bias[2 * j + 1]);
            *(uint4*)(g_h16 + (size_t)gn * (OUT_FEATS / 2) + g_o * 4) = *(uint4*)p;
        }
    }
}

// ---------------------------------------------------------------------------
// Kernel 3: edge scatter. 16 threads per edge, each owns 4 floats of the
// output row. Gather 8B of fp16 h per lane (128B/edge, one cache line),
// convert+scale, ONE contiguous red.v4 per lane (R4 pattern: 4 full
// 128B lines per warp at the LTS, no partial wavefronts).
// ---------------------------------------------------------------------------
__global__ __launch_bounds__(256) void edge_kernel(
    const float* __restrict__ e,
    float*       __restrict__ out)
{
    long long idx = (long long)blockIdx.x * blockDim.x + threadIdx.x;
    int eid  = (int)(idx >> 4);
    int lane = (int)(idx & 15);
    if (eid >= N_EDGES) return;

    int   s = g_src32[eid];
    int   d = g_dst32[eid];
    float w = e[eid];

    // 4 halves = 8B per lane; 16 lanes cover the 128B fp16 row
    uint2 raw = *(const uint2*)(g_h16 + (size_t)s * (OUT_FEATS / 2) + lane * 2);
    float2 f0 = __half22float2(*(__half2*)&raw.x);
    float2 f1 = __half22float2(*(__half2*)&raw.y);

    red_add_v4(out + (size_t)d * OUT_FEATS + lane * 4,
               f0.x * w, f0.y * w, f1.x * w, f1.y * w);
}

// ---------------------------------------------------------------------------
// Kernel 4: in-place relu
// ---------------------------------------------------------------------------
__global__ __launch_bounds__(256) void relu_kernel(float4* out, int n4) {
    int i = blockIdx.x * blockDim.x + threadIdx.x;
    if (i < n4) {
        float4 v = out[i];
        v.x = fmaxf(v.x, 0.f);
        v.y = fmaxf(v.y, 0.f);
        v.z = fmaxf(v.z, 0.f);
        v.w = fmaxf(v.w, 0.f);
        out[i] = v;
    }
}

// ---------------------------------------------------------------------------
extern "C" void kernel_launch(void* const* d_in, const int* in_sizes, int n_in,
                              void* d_out, int out_size)
{
    const float* feat = (const float*)d_in[0];
    const void*  src  = d_in[1];
    const void*  dst  = d_in[2];
    const float* e    = (const float*)d_in[3];
    const float* W_w  = (const float*)d_in[4];
    const float* W_b  = (const float*)d_in[5];
    float*       out  = (float*)d_out;

    const int n4 = (N_NODES * OUT_FEATS) / 4;   // 1.6M float4

    // 1. zero accumulator + clear flag
    zero_kernel<<<(n4 + 255) / 256, 256>>>((float4*)out, n4);

    // 1b. detect index dtype (int32 vs int64)
    detect_kernel<<<1024, 256>>>((const unsigned int*)src);

    // 1c. normalize indices to int32
    convert_kernel<<<(N_EDGES + 255) / 256, 256>>>(src, dst);

    // 2. dense projection into g_h16 (fp16)
    gemm_kernel<<<(N_NODES + MT - 1) / MT, 128>>>(feat, W_w, W_b);

    // 3. edge gather/scale/scatter-add (16 threads per edge)
    {
        long long total_threads = (long long)N_EDGES * 16LL;
        int blocks = (int)((total_threads + 255) / 256);   // 100000 blocks
        edge_kernel<<<blocks, 256>>>(e, out);
    }

    // 4. relu in place
    relu_kernel<<<(n4 + 255) / 256, 256>>>((float4*)out, n4);
}

// round 7
// speedup vs baseline: 1.4690x; 1.3074x over previous
#include <cuda_runtime.h>
#include <cuda_fp16.h>
#include <cuda_bf16.h>

// Problem constants (fixed shapes per reference)
#define N_NODES   100000
#define N_EDGES   1600000
#define IN_FEATS  128
#define OUT_FEATS 64

// Scan configuration: 196 blocks x 512 items covers 100352 >= N_NODES
#define SCAN_BLOCKS 196
#define SCAN_CHUNK  512

// Scratch: projected features h in fp16 (12.8 MB)
__device__ __half2 g_h16[(size_t)N_NODES * (OUT_FEATS / 2)];
// Scratch: int32 edge indices (dtype-normalized)
__device__ int g_src32[N_EDGES];
__device__ int g_dst32[N_EDGES];
// CSR build: counts -> cursors, offsets, block partial sums
__device__ int g_cnt[N_NODES];          // counts, then write cursors
__device__ int g_off[N_NODES + 1];      // segment offsets
__device__ int g_bsum[SCAN_BLOCKS];     // per-block sums
__device__ int g_bbase[SCAN_BLOCKS];    // per-block exclusive bases
// dst-sorted edges: (src, bitcast(e))
__device__ int2 g_edge[N_EDGES];
// Dtype detection flag: nonzero => index buffers are int32
__device__ unsigned int g_is_i32;

// ---------------------------------------------------------------------------
// Kernel 0: clear counters + detection flag
// ---------------------------------------------------------------------------
__global__ __launch_bounds__(256) void prep_kernel() {
    int i = blockIdx.x * blockDim.x + threadIdx.x;
    if (i == 0) g_is_i32 = 0u;
    if (i < N_NODES) g_cnt[i] = 0;
}

// ---------------------------------------------------------------------------
// Kernel 1: dtype detection. Odd 4B words within the first 4*N_EDGES bytes
// are int64 high words (all zero since idx < 100000) or real int32 indices.
// ---------------------------------------------------------------------------
__global__ __launch_bounds__(256) void detect_kernel(const unsigned int* __restrict__ buf) {
    unsigned int lor = 0;
    int nhalf = N_EDGES / 2;
    for (int i = blockIdx.x * blockDim.x + threadIdx.x;
         i < nhalf;
         i += gridDim.x * blockDim.x) {
        lor |= buf[2 * i + 1];
    }
    unsigned int any = __ballot_sync(0xffffffffu, lor != 0u);
    if ((threadIdx.x & 31) == 0 && any) g_is_i32 = 1u;  // same-value store, race-free
}

// ---------------------------------------------------------------------------
// Kernel 2: normalize indices to int32 (bounds clamp) + count dst histogram
// ---------------------------------------------------------------------------
__global__ __launch_bounds__(256) void convert_count_kernel(const void* __restrict__ srcb,
                                                            const void* __restrict__ dstb) {
    int i = blockIdx.x * blockDim.x + threadIdx.x;
    if (i >= N_EDGES) return;
    unsigned int i32 = g_is_i32;
    int s, d;
    if (i32) {
        s = ((const int*)srcb)[i];
        d = ((const int*)dstb)[i];
    } else {
        s = (int)((const long long*)srcb)[i];
        d = (int)((const long long*)dstb)[i];
    }
    s = ((unsigned)s < (unsigned)N_NODES) ? s : 0;
    d = ((unsigned)d < (unsigned)N_NODES) ? d : 0;
    g_src32[i] = s;
    g_dst32[i] = d;
    atomicAdd(&g_cnt[d], 1);
}

// ---------------------------------------------------------------------------
// Scan kernels: exclusive prefix sum of g_cnt -> g_off, cursors in g_cnt.
// ---------------------------------------------------------------------------
__global__ __launch_bounds__(SCAN_CHUNK) void scan1_kernel() {
    __shared__ int sh[SCAN_CHUNK];
    int t = threadIdx.x;
    int i = blockIdx.x * SCAN_CHUNK + t;
    sh[t] = (i < N_NODES) ? g_cnt[i] : 0;
    __syncthreads();
    // tree reduce
    for (int ofs = SCAN_CHUNK / 2; ofs > 0; ofs >>= 1) {
        if (t < ofs) sh[t] += sh[t + ofs];
        __syncthreads();
    }
    if (t == 0) g_bsum[blockIdx.x] = sh[0];
}

__global__ __launch_bounds__(256) void scan2_kernel() {
    __shared__ int sh[256];
    int t = threadIdx.x;
    int v = (t < SCAN_BLOCKS) ? g_bsum[t] : 0;
    sh[t] = v;
    __syncthreads();
    // Hillis-Steele inclusive scan over 256
    for (int ofs = 1; ofs < 256; ofs <<= 1) {
        int x = (t >= ofs) ? sh[t - ofs] : 0;
        __syncthreads();
        sh[t] += x;
        __syncthreads();
    }
    if (t < SCAN_BLOCKS) g_bbase[t] = sh[t] - v;   // exclusive
    if (t == 0) g_off[N_NODES] = N_EDGES;
}

__global__ __launch_bounds__(SCAN_CHUNK) void scan3_kernel() {
    __shared__ int sh[SCAN_CHUNK];
    int t = threadIdx.x;
    int i = blockIdx.x * SCAN_CHUNK + t;
    int v = (i < N_NODES) ? g_cnt[i] : 0;
    sh[t] = v;
    __syncthreads();
    for (int ofs = 1; ofs < SCAN_CHUNK; ofs <<= 1) {
        int x = (t >= ofs) ? sh[t - ofs] : 0;
        __syncthreads();
        sh[t] += x;
        __syncthreads();
    }
    if (i < N_NODES) {
        int off = sh[t] - v + g_bbase[blockIdx.x];  // exclusive + block base
        g_off[i] = off;
        g_cnt[i] = off;                              // becomes write cursor
    }
}

// ---------------------------------------------------------------------------
// Kernel 3: scatter edges into dst-sorted order
// ---------------------------------------------------------------------------
__global__ __launch_bounds__(256) void scatter_kernel(const float* __restrict__ e) {
    int i = blockIdx.x * blockDim.x + threadIdx.x;
    if (i >= N_EDGES) return;
    int d = g_dst32[i];
    int pos = atomicAdd(&g_cnt[d], 1);
    g_edge[pos] = make_int2(g_src32[i], __float_as_int(e[i]));
}

// ---------------------------------------------------------------------------
// Kernel 4: tiled fp32 GEMM  h[n][o] = sum_k feat[n][k] * W[o][k] + b[o]
// (unchanged — at the fp32-FFMA issue roofline)
// ---------------------------------------------------------------------------
#define MT 128
#define KT 32

__global__ __launch_bounds__(128) void gemm_kernel(
    const float* __restrict__ feat,
    const float* __restrict__ W,
    const float* __restrict__ b)
{
    __shared__ float sf[KT][MT];        // feat tile: [k][node^swz]  (16KB)
    __shared__ float sw[KT][OUT_FEATS]; // W tile:    [k][out ^swz]  (8KB)

    const int tid    = threadIdx.x;
    const int block0 = blockIdx.x * MT;
    const int g_n    = tid & 15;
    const int g_o    = tid >> 4;
    const int nr     = g_n * 8;
    const int oc     = g_o * 8;

    float acc[8][8];
#pragma unroll
    for (int i = 0; i < 8; i++)
#pragma unroll
        for (int j = 0; j < 8; j++) acc[i][j] = 0.f;

    for (int kb = 0; kb < IN_FEATS; kb += KT) {
#pragma unroll
        for (int t = 0; t < 8; t++) {
            int l    = tid + t * 128;
            int node = l >> 3;
            int kq   = l & 7;
            float4 v = make_float4(0.f, 0.f, 0.f, 0.f);
            int gn = block0 + node;
            if (gn < N_NODES)
                v = *(const float4*)(feat + (size_t)gn * IN_FEATS + kb + kq * 4);
            int col = node ^ ((kq & 3) << 3);
            sf[kq * 4 + 0][col] = v.x;
            sf[kq * 4 + 1][col] = v.y;
            sf[kq * 4 + 2][col] = v.z;
            sf[kq * 4 + 3][col] = v.w;
        }
#pragma unroll
        for (int t = 0; t < 4; t++) {
            int l  = tid + t * 128;
            int o  = l >> 3;
            int kq = l & 7;
            float4 v = *(const float4*)(W + (size_t)o * IN_FEATS + kb + kq * 4);
            int col = o ^ ((kq & 3) << 3);
            sw[kq * 4 + 0][col] = v.x;
            sw[kq * 4 + 1][col] = v.y;
            sw[kq * 4 + 2][col] = v.z;
            sw[kq * 4 + 3][col] = v.w;
        }
        __syncthreads();

#pragma unroll
        for (int kk = 0; kk < KT; kk++) {
            int swz = ((kk >> 2) & 3) << 3;
            float a[8], w[8];
            *(float4*)&a[0] = *(const float4*)&sf[kk][(nr ^ swz)];
            *(float4*)&a[4] = *(const float4*)&sf[kk][(nr ^ swz) + 4];
            *(float4*)&w[0] = *(const float4*)&sw[kk][(oc ^ swz)];
            *(float4*)&w[4] = *(const float4*)&sw[kk][(oc ^ swz) + 4];
#pragma unroll
            for (int i = 0; i < 8; i++)
#pragma unroll
                for (int j = 0; j < 8; j++)
                    acc[i][j] += a[i] * w[j];
        }
        __syncthreads();
    }

    float bias[8];
    *(float4*)&bias[0] = *(const float4*)(b + oc);
    *(float4*)&bias[4] = *(const float4*)(b + oc + 4);
#pragma unroll
    for (int i = 0; i < 8; i++) {
        int gn = block0 + nr + i;
        if (gn < N_NODES) {
            __half2 p[4];
#pragma unroll
            for (int j = 0; j < 4; j++)
                p[j] = __floats2half2_rn(acc[i][2 * j] + bias[2 * j],
                                         acc[i][2 * j + 1] + bias[2 * j + 1]);
            *(uint4*)(g_h16 + (size_t)gn * (OUT_FEATS / 2) + g_o * 4) = *(uint4*)p;
        }
    }
}

// ---------------------------------------------------------------------------
// Kernel 5: owner-computes reduce. 16 lanes per node stream the node's edge
// segment: broadcast (src, e), gather one 128B fp16 row per edge (8B/lane),
// accumulate fp32 in registers, single relu'd float4 store per lane.
// No atomics. Every output row written exactly once (zeros for deg-0 nodes).
// ---------------------------------------------------------------------------
__global__ __launch_bounds__(256) void reduce_kernel(float* __restrict__ out) {
    int tid   = threadIdx.x;
    int group = tid >> 4;               // 16 groups per block
    int lane  = tid & 15;
    int n     = blockIdx.x * 16 + group;
    if (n >= N_NODES) return;

    int beg = g_off[n];
    int end = g_off[n + 1];

    float ax = 0.f, ay = 0.f, az = 0.f, aw = 0.f;

#pragma unroll 2
    for (int i = beg; i < end; i++) {
        int2  ed = g_edge[i];           // broadcast across 16 lanes
        int   s  = ed.x;
        float w  = __int_as_float(ed.y);
        uint2 raw = *(const uint2*)(g_h16 + (size_t)s * (OUT_FEATS / 2) + lane * 2);
        float2 f0 = __half22float2(*(const __half2*)&raw.x);
        float2 f1 = __half22float2(*(const __half2*)&raw.y);
        ax += f0.x * w;
        ay += f0.y * w;
        az += f1.x * w;
        aw += f1.y * w;
    }

    float4 r;
    r.x = fmaxf(ax, 0.f);
    r.y = fmaxf(ay, 0.f);
    r.z = fmaxf(az, 0.f);
    r.w = fmaxf(aw, 0.f);
    *(float4*)(out + (size_t)n * OUT_FEATS + lane * 4) = r;
}

// ---------------------------------------------------------------------------
extern "C" void kernel_launch(void* const* d_in, const int* in_sizes, int n_in,
                              void* d_out, int out_size)
{
    const float* feat = (const float*)d_in[0];
    const void*  src  = d_in[1];
    const void*  dst  = d_in[2];
    const float* e    = (const float*)d_in[3];
    const float* W_w  = (const float*)d_in[4];
    const float* W_b  = (const float*)d_in[5];
    float*       out  = (float*)d_out;

    // 0. clear counters + flag
    prep_kernel<<<(N_NODES + 255) / 256, 256>>>();

    // 1. detect index dtype (int32 vs int64)
    detect_kernel<<<1024, 256>>>((const unsigned int*)src);

    // 2. normalize indices + dst histogram
    convert_count_kernel<<<(N_EDGES + 255) / 256, 256>>>(src, dst);

    // 2b. exclusive scan -> offsets + cursors
    scan1_kernel<<<SCAN_BLOCKS, SCAN_CHUNK>>>();
    scan2_kernel<<<1, 256>>>();
    scan3_kernel<<<SCAN_BLOCKS, SCAN_CHUNK>>>();

    // 3. scatter edges into dst-sorted order
    scatter_kernel<<<(N_EDGES + 255) / 256, 256>>>(e);

    // 4. dense projection into g_h16 (fp16)
    gemm_kernel<<<(N_NODES + MT - 1) / MT, 128>>>(feat, W_w, W_b);

    // 5. owner-computes gather/reduce with fused relu (writes all rows)
    reduce_kernel<<<(N_NODES + 15) / 16, 256>>>(out);
}

// round 10
// speedup vs baseline: 1.7953x; 1.2221x over previous
#include <cuda_runtime.h>
#include <cuda_fp16.h>
#include <cuda_bf16.h>

// Problem constants (fixed shapes per reference)
#define N_NODES   100000
#define N_EDGES   1600000
#define IN_FEATS  128
#define OUT_FEATS 64

// Scan configuration: 196 blocks x 512 items covers 100352 >= N_NODES
#define SCAN_BLOCKS 196
#define SCAN_CHUNK  512

// Scratch: projected features h in fp16 (12.8 MB)
__device__ __half2 g_h16[(size_t)N_NODES * (OUT_FEATS / 2)];
// Scratch: int32 edge indices (dtype-normalized)
__device__ int g_src32[N_EDGES];
__device__ int g_dst32[N_EDGES];
// CSR build: counts -> cursors, offsets, block partial sums
__device__ int g_cnt[N_NODES];          // counts, then write cursors
__device__ int g_off[N_NODES + 1];      // segment offsets
__device__ int g_bsum[SCAN_BLOCKS];     // per-block sums
__device__ int g_bbase[SCAN_BLOCKS];    // per-block exclusive bases
// dst-sorted edges: (src, bitcast(e))
__device__ int2 g_edge[N_EDGES];
// Dtype flag: statically 0; detect sets to 1 iff buffers are int32.
// Idempotent across graph replays (input data is constant), so no clear pass.
__device__ unsigned int g_is_i32 = 0u;

// ---------------------------------------------------------------------------
// Kernel 1: dtype detection + g_cnt zeroing. Odd 4B words within the first
// 4*N_EDGES bytes are int64 high words (all zero since idx < 100000) or real
// int32 indices (almost surely some nonzero).
// ---------------------------------------------------------------------------
__global__ __launch_bounds__(256) void detect_kernel(const unsigned int* __restrict__ buf) {
    int gid = blockIdx.x * blockDim.x + threadIdx.x;
    if (gid < N_NODES) g_cnt[gid] = 0;

    unsigned int lor = 0;
    int nhalf = N_EDGES / 2;
    for (int i = gid; i < nhalf; i += gridDim.x * blockDim.x)
        lor |= buf[2 * i + 1];
    unsigned int any = __ballot_sync(0xffffffffu, lor != 0u);
    if ((threadIdx.x & 31) == 0 && any) g_is_i32 = 1u;  // same-value store, race-free
}

// ---------------------------------------------------------------------------
// Kernel 2: normalize indices to int32 (bounds clamp) + count dst histogram
// ---------------------------------------------------------------------------
__global__ __launch_bounds__(256) void convert_count_kernel(const void* __restrict__ srcb,
                                                            const void* __restrict__ dstb) {
    int i = blockIdx.x * blockDim.x + threadIdx.x;
    if (i >= N_EDGES) return;
    unsigned int i32 = g_is_i32;
    int s, d;
    if (i32) {
        s = ((const int*)srcb)[i];
        d = ((const int*)dstb)[i];
    } else {
        s = (int)((const long long*)srcb)[i];
        d = (int)((const long long*)dstb)[i];
    }
    s = ((unsigned)s < (unsigned)N_NODES) ? s : 0;
    d = ((unsigned)d < (unsigned)N_NODES) ? d : 0;
    g_src32[i] = s;
    g_dst32[i] = d;
    atomicAdd(&g_cnt[d], 1);
}

// ---------------------------------------------------------------------------
// Scan kernels: exclusive prefix sum of g_cnt -> g_off, cursors in g_cnt.
// ---------------------------------------------------------------------------
__global__ __launch_bounds__(SCAN_CHUNK) void scan1_kernel() {
    __shared__ int sh[SCAN_CHUNK];
    int t = threadIdx.x;
    int i = blockIdx.x * SCAN_CHUNK + t;
    sh[t] = (i < N_NODES) ? g_cnt[i] : 0;
    __syncthreads();
    for (int ofs = SCAN_CHUNK / 2; ofs > 0; ofs >>= 1) {
        if (t < ofs) sh[t] += sh[t + ofs];
        __syncthreads();
    }
    if (t == 0) g_bsum[blockIdx.x] = sh[0];
}

__global__ __launch_bounds__(256) void scan2_kernel() {
    __shared__ int sh[256];
    int t = threadIdx.x;
    int v = (t < SCAN_BLOCKS) ? g_bsum[t] : 0;
    sh[t] = v;
    __syncthreads();
    for (int ofs = 1; ofs < 256; ofs <<= 1) {
        int x = (t >= ofs) ? sh[t - ofs] : 0;
        __syncthreads();
        sh[t] += x;
        __syncthreads();
    }
    if (t < SCAN_BLOCKS) g_bbase[t] = sh[t] - v;   // exclusive
    if (t == 0) g_off[N_NODES] = N_EDGES;
}

__global__ __launch_bounds__(SCAN_CHUNK) void scan3_kernel() {
    __shared__ int sh[SCAN_CHUNK];
    int t = threadIdx.x;
    int i = blockIdx.x * SCAN_CHUNK + t;
    int v = (i < N_NODES) ? g_cnt[i] : 0;
    sh[t] = v;
    __syncthreads();
    for (int ofs = 1; ofs < SCAN_CHUNK; ofs <<= 1) {
        int x = (t >= ofs) ? sh[t - ofs] : 0;
        __syncthreads();
        sh[t] += x;
        __syncthreads();
    }
    if (i < N_NODES) {
        int off = sh[t] - v + g_bbase[blockIdx.x];  // exclusive + block base
        g_off[i] = off;
        g_cnt[i] = off;                              // becomes write cursor
    }
}

// ---------------------------------------------------------------------------
// Kernel 3: scatter edges into dst-sorted order
// ---------------------------------------------------------------------------
__global__ __launch_bounds__(256) void scatter_kernel(const float* __restrict__ e) {
    int i = blockIdx.x * blockDim.x + threadIdx.x;
    if (i >= N_EDGES) return;
    int d = g_dst32[i];
    int pos = atomicAdd(&g_cnt[d], 1);
    g_edge[pos] = make_int2(g_src32[i], __float_as_int(e[i]));
}

// ---------------------------------------------------------------------------
// Kernel 4: fp16 tensor-core GEMM via mma.sync.m16n8k16.
// Block = 128 threads (4 warps), tile = 64 nodes x 64 outs x full K=128.
// Static smem 34.8KB: A 64x136 fp16, B 64x136 fp16 (+8-half pad -> fragment
// row stride = 68 words, banks (4g+q) all distinct -> conflict-free).
// fp32->fp16 conversion fused into the smem fill. Warp w owns rows
// [16w, 16w+16): 1 m16-tile x 8 n8-tiles x 8 k16-steps = 64 MMAs/warp.
// ---------------------------------------------------------------------------
#define GM 64           // nodes per block
#define APAD 136        // padded row length in halves (128 + 8)

__device__ __forceinline__ void mma16816(float* d, unsigned a0, unsigned a1,
                                         unsigned a2, unsigned a3,
                                         unsigned b0, unsigned b1) {
    asm volatile(
        "mma.sync.aligned.m16n8k16.row.col.f32.f16.f16.f32 "
        "{%0,%1,%2,%3}, {%4,%5,%6,%7}, {%8,%9}, {%0,%1,%2,%3};"
        : "+f"(d[0]), "+f"(d[1]), "+f"(d[2]), "+f"(d[3])
        : "r"(a0), "r"(a1), "r"(a2), "r"(a3), "r"(b0), "r"(b1));
}

__global__ __launch_bounds__(128) void gemm_hmma_kernel(
    const float* __restrict__ feat,
    const float* __restrict__ W,
    const float* __restrict__ b)
{
    __shared__ __align__(16) __half Asm[GM][APAD];        // 17.4 KB
    __shared__ __align__(16) __half Bsm[OUT_FEATS][APAD]; // 17.4 KB

    const int tid    = threadIdx.x;
    const int lane   = tid & 31;
    const int warp   = tid >> 5;
    const int block0 = blockIdx.x * GM;
    const int g      = lane >> 2;   // group id 0..7
    const int q      = lane & 3;    // quad id 0..3

    // ---- fill A: 64 rows x 32 float4 = 2048 loads, 16 per thread ----
#pragma unroll
    for (int t = 0; t < 16; t++) {
        int l   = tid + t * 128;     // 0..2047
        int row = l >> 5;            // 0..63
        int kq  = l & 31;            // float4 index 0..31
        float4 v = make_float4(0.f, 0.f, 0.f, 0.f);
        int gn = block0 + row;
        if (gn < N_NODES)
            v = *(const float4*)(feat + (size_t)gn * IN_FEATS + kq * 4);
        __half2 h0 = __floats2half2_rn(v.x, v.y);
        __half2 h1 = __floats2half2_rn(v.z, v.w);
        uint2 pk;
        pk.x = *(unsigned*)&h0;
        pk.y = *(unsigned*)&h1;
        *(uint2*)&Asm[row][kq * 4] = pk;
    }
    // ---- fill B: 64 rows x 32 float4 = 2048 loads, 16 per thread ----
#pragma unroll
    for (int t = 0; t < 16; t++) {
        int l   = tid + t * 128;     // 0..2047
        int row = l >> 5;            // 0..63
        int kq  = l & 31;
        float4 v = *(const float4*)(W + (size_t)row * IN_FEATS + kq * 4);
        __half2 h0 = __floats2half2_rn(v.x, v.y);
        __half2 h1 = __floats2half2_rn(v.z, v.w);
        uint2 pk;
        pk.x = *(unsigned*)&h0;
        pk.y = *(unsigned*)&h1;
        *(uint2*)&Bsm[row][kq * 4] = pk;
    }
    __syncthreads();

    float acc[8][4];
#pragma unroll
    for (int nt = 0; nt < 8; nt++)
#pragma unroll
        for (int j = 0; j < 4; j++) acc[nt][j] = 0.f;

#pragma unroll
    for (int ks = 0; ks < 8; ks++) {
        int kc = ks * 16 + q * 2;
        int r  = warp * 16 + g;
        unsigned a0 = *(const unsigned*)&Asm[r][kc];
        unsigned a1 = *(const unsigned*)&Asm[r + 8][kc];
        unsigned a2 = *(const unsigned*)&Asm[r][kc + 8];
        unsigned a3 = *(const unsigned*)&Asm[r + 8][kc + 8];
#pragma unroll
        for (int nt = 0; nt < 8; nt++) {
            unsigned b0 = *(const unsigned*)&Bsm[nt * 8 + g][kc];
            unsigned b1 = *(const unsigned*)&Bsm[nt * 8 + g][kc + 8];
            mma16816(acc[nt], a0, a1, a2, a3, b0, b1);
        }
    }

    // ---- epilogue: bias + fp16 store (c0,c1 = row g; c2,c3 = row g+8) ----
#pragma unroll
    for (int nt = 0; nt < 8; nt++) {
        int col = nt * 8 + q * 2;
        float bx = b[col];
        float by = b[col + 1];
        int r0 = block0 + warp * 16 + g;
        if (r0 < N_NODES) {
            __half2 h = __floats2half2_rn(acc[nt][0] + bx, acc[nt][1] + by);
            g_h16[(size_t)r0 * (OUT_FEATS / 2) + (col >> 1)] = h;
        }
        int r1 = r0 + 8;
        if (r1 < N_NODES) {
            __half2 h = __floats2half2_rn(acc[nt][2] + bx, acc[nt][3] + by);
            g_h16[(size_t)r1 * (OUT_FEATS / 2) + (col >> 1)] = h;
        }
    }
}

// ---------------------------------------------------------------------------
// Kernel 5: owner-computes reduce. 16 lanes per node stream the node's edge
// segment: broadcast (src, e), gather one 128B fp16 row per edge (8B/lane),
// accumulate fp32 in registers, single relu'd float4 store per lane.
// No atomics. Every output row written exactly once (zeros for deg-0 nodes).
// ---------------------------------------------------------------------------
__global__ __launch_bounds__(256) void reduce_kernel(float* __restrict__ out) {
    int tid   = threadIdx.x;
    int group = tid >> 4;               // 16 groups per block
    int lane  = tid & 15;
    int n     = blockIdx.x * 16 + group;
    if (n >= N_NODES) return;

    int beg = g_off[n];
    int end = g_off[n + 1];

    float ax = 0.f, ay = 0.f, az = 0.f, aw = 0.f;

#pragma unroll 2
    for (int i = beg; i < end; i++) {
        int2  ed = g_edge[i];           // broadcast across 16 lanes
        int   s  = ed.x;
        float w  = __int_as_float(ed.y);
        uint2 raw = *(const uint2*)(g_h16 + (size_t)s * (OUT_FEATS / 2) + lane * 2);
        float2 f0 = __half22float2(*(const __half2*)&raw.x);
        float2 f1 = __half22float2(*(const __half2*)&raw.y);
        ax += f0.x * w;
        ay += f0.y * w;
        az += f1.x * w;
        aw += f1.y * w;
    }

    float4 r;
    r.x = fmaxf(ax, 0.f);
    r.y = fmaxf(ay, 0.f);
    r.z = fmaxf(az, 0.f);
    r.w = fmaxf(aw, 0.f);
    *(float4*)(out + (size_t)n * OUT_FEATS + lane * 4) = r;
}

// ---------------------------------------------------------------------------
extern "C" void kernel_launch(void* const* d_in, const int* in_sizes, int n_in,
                              void* d_out, int out_size)
{
    const float* feat = (const float*)d_in[0];
    const void*  src  = d_in[1];
    const void*  dst  = d_in[2];
    const float* e    = (const float*)d_in[3];
    const float* W_w  = (const float*)d_in[4];
    const float* W_b  = (const float*)d_in[5];
    float*       out  = (float*)d_out;

    // 1. detect index dtype + zero counters
    detect_kernel<<<1024, 256>>>((const unsigned int*)src);

    // 2. normalize indices + dst histogram
    convert_count_kernel<<<(N_EDGES + 255) / 256, 256>>>(src, dst);

    // 2b. exclusive scan -> offsets + cursors
    scan1_kernel<<<SCAN_BLOCKS, SCAN_CHUNK>>>();
    scan2_kernel<<<1, 256>>>();
    scan3_kernel<<<SCAN_BLOCKS, SCAN_CHUNK>>>();

    // 3. scatter edges into dst-sorted order
    scatter_kernel<<<(N_EDGES + 255) / 256, 256>>>(e);

    // 4. dense projection into g_h16 (fp16, tensor cores)
    gemm_hmma_kernel<<<(N_NODES + GM - 1) / GM, 128>>>(feat, W_w, W_b);

    // 5. owner-computes gather/reduce with fused relu (writes all rows)
    reduce_kernel<<<(N_NODES + 15) / 16, 256>>>(out);
}